// round 1
// baseline (speedup 1.0000x reference)
#include <cuda_runtime.h>
#include <cuda_bf16.h>

// PostProcessor3D: threshold -> 5x5x5 max-pool (stride 1, pad 2) -> strict peak mask.
// Input:  [1,1,64,512,512] fp32.  Output: [64,512,512] fp32.
//
// Fused single kernel. Each block owns a 32(W) x 16(H) tile and marches along D
// with a 5-plane register ring of separable 2-D (5x5) maxima.
// -inf padding is equivalent to 0 padding here (all thresholded values >= 0,
// every window contains at least one in-range value).

#define TW 32
#define TH 16
#define HW (TW + 4)   // 36
#define HH (TH + 4)   // 20
#define DD 64
#define Hteam 512
#define HDIM 512
#define WDIM 512
#define THRESH 0.9f

__global__ __launch_bounds__(512, 2)
void peak3d_kernel(const float* __restrict__ in, float* __restrict__ out) {
    // plane padded to 40 columns to keep LDS bank behavior sane
    __shared__ float plane[HH][HW + 4];
    __shared__ float wmax[HH][TW];

    const int tx  = threadIdx.x;          // 0..31
    const int ty  = threadIdx.y;          // 0..15
    const int tid = ty * TW + tx;         // 0..511
    const int bw  = blockIdx.x * TW;      // tile origin in W
    const int bh  = blockIdx.y * TH;      // tile origin in H

    const int gw = bw + tx;
    const int gh = bh + ty;

    // 5-deep rings: r* = 2-D (5x5) max of thresholded plane, c* = thresholded center
    float r0 = 0.f, r1 = 0.f, r2 = 0.f, r3 = 0.f, r4 = 0.f;
    float c0 = 0.f, c1 = 0.f, c2 = 0.f, c3 = 0.f, c4 = 0.f;

    for (int dl = 0; dl <= DD + 1; ++dl) {
        float m2  = 0.f;   // 2-D max for plane dl (0 if dl out of range -> pad)
        float cen = 0.f;   // thresholded center value for plane dl

        if (dl < DD) {
            // ---- load thresholded plane (with 2-wide halo) into smem ----
            const float* src = in + (size_t)dl * (HDIM * WDIM);
            #pragma unroll
            for (int i = tid; i < HH * HW; i += 512) {
                int r = i / HW, c = i % HW;
                int ghh = bh + r - 2;
                int gww = bw + c - 2;
                float v = 0.f;
                if (ghh >= 0 && ghh < HDIM && gww >= 0 && gww < WDIM) {
                    float x = __ldg(src + (size_t)ghh * WDIM + gww);
                    v = (x > THRESH) ? x : 0.f;
                }
                plane[r][c] = v;
            }
            __syncthreads();

            // ---- separable W-max (window 5) for all HH rows x TW cols ----
            #pragma unroll
            for (int i = tid; i < HH * TW; i += 512) {
                int r = i / TW, c = i % TW;
                float m = plane[r][c];
                m = fmaxf(m, plane[r][c + 1]);
                m = fmaxf(m, plane[r][c + 2]);
                m = fmaxf(m, plane[r][c + 3]);
                m = fmaxf(m, plane[r][c + 4]);
                wmax[r][c] = m;
            }
            __syncthreads();

            // ---- H-max (window 5), one output per thread ----
            float m = wmax[ty][tx];
            m = fmaxf(m, wmax[ty + 1][tx]);
            m = fmaxf(m, wmax[ty + 2][tx]);
            m = fmaxf(m, wmax[ty + 3][tx]);
            m = fmaxf(m, wmax[ty + 4][tx]);
            m2  = m;
            cen = plane[ty + 2][tx + 2];
            __syncthreads();   // protect smem before next plane's load
        }

        // shift rings: after this, r4 = plane dl, r3 = dl-1, ..., r0 = dl-4
        r0 = r1; r1 = r2; r2 = r3; r3 = r4; r4 = m2;
        c0 = c1; c1 = c2; c2 = c3; c3 = c4; c4 = cen;

        if (dl >= 2) {
            const int od = dl - 2;  // output depth; window = planes od-2..od+2
            float mp = fmaxf(fmaxf(fmaxf(r0, r1), fmaxf(r2, r3)), r4);
            // center plane of the window is od -> ring slot c2
            float o = (mp > 0.f && mp == c2) ? mp : 0.f;
            out[(size_t)od * (HDIM * WDIM) + (size_t)gh * WDIM + gw] = o;
        }
    }
    (void)c0; (void)c4;
}

extern "C" void kernel_launch(void* const* d_in, const int* in_sizes, int n_in,
                              void* d_out, int out_size) {
    (void)in_sizes; (void)n_in; (void)out_size;
    const float* in = (const float*)d_in[0];
    float* out = (float*)d_out;
    dim3 block(TW, TH);                      // 512 threads
    dim3 grid(WDIM / TW, HDIM / TH);         // 16 x 32 = 512 blocks
    peak3d_kernel<<<grid, block>>>(in, out);
}

// round 3
// speedup vs baseline: 1.9154x; 1.9154x over previous
#include <cuda_runtime.h>
#include <cuda_bf16.h>

// PostProcessor3D: threshold(0.9) -> 5x5x5 maxpool(stride1,pad2) -> strict peak mask.
// In: [64,512,512] f32.  Out: [64,512,512] f32.
//
// Block (128,8) = 1024 threads covers full W=512 (float4/thread) x 8 H rows,
// marching 36 planes of a 32-deep D chunk. Grid 64x2 = 128 blocks (one wave).
// Separable max: W-max (smem) -> H-max (smem) -> D via register rings.
// -inf pad == 0 pad since thresholded values >= 0.
//
// Peak identity (fixed ring depth):
//   s(p)   = (cen(p)==m2d(p)) ? cen(p) : 0              (at plane p)
//   cn(p)  = (s >= m2d(p-1) && s >= m2d(p-2)) ? s : 0   (at plane p)
//   out(q) = (cn(q) >= m2d(q+1) && cn(q) >= m2d(q+2)) ? cn(q) : 0
//   emitted at iteration p=q+2 with a 2-deep ring: cnd0 = cn(p-2).

#define Wd 512
#define Hd 512
#define Dd 64
#define TH 8            // output rows per block
#define LR 12           // loaded rows (TH + 4)
#define DCH 32          // output planes per block
#define NP (DCH + 4)    // planes iterated
#define VST 520         // vsm row stride (512 + 4 halo + pad)
#define THRESH 0.9f

__device__ __forceinline__ float thr(float x) { return x > THRESH ? x : 0.f; }
__device__ __forceinline__ float4 fmax4(float4 a, float4 b) {
    return make_float4(fmaxf(a.x, b.x), fmaxf(a.y, b.y),
                       fmaxf(a.z, b.z), fmaxf(a.w, b.w));
}

extern __shared__ float sm[];   // vsm[2][LR][VST] then wsm[2][LR][512]

__global__ __launch_bounds__(1024, 1)
void peak3d_kernel(const float* __restrict__ in, float* __restrict__ out) {
    const int tx = threadIdx.x;          // 0..127
    const int ty = threadIdx.y;          // 0..7
    const int c  = tx << 2;              // column base (float4)
    const int h0 = blockIdx.x * TH;
    const int d0 = blockIdx.y * DCH;

    float* vsm = sm;                         // thresholded planes, 2 buffers
    float* wsm = sm + 2 * LR * VST;          // W-max planes, 2 buffers

    // zero the W-halo slots (cols -2,-1,512,513 -> idx 0,1,514,515) once
    {
        int tid = ty * 128 + tx;
        if (tid < 2 * LR) {
            float* r = vsm + tid * VST;
            r[0] = 0.f; r[1] = 0.f; r[514] = 0.f; r[515] = 0.f;
        }
    }

    const int  k2   = 8 + ty;
    const bool has2 = (ty < 4);
    const int  gh1  = h0 - 2 + ty;
    const int  gh2  = h0 - 2 + k2;
    const bool ok1  = ((unsigned)gh1 < (unsigned)Hd);
    const bool ok2  = has2 && (gh2 < Hd);

    // ---- prefetch plane p=0 (dl = d0-2) and store into buffer 0 ----
    float4 a1 = make_float4(0.f, 0.f, 0.f, 0.f), a2 = a1;
    {
        int dl = d0 - 2;
        if (dl >= 0) {
            const float* pl = in + dl * (Hd * Wd);
            if (ok1) a1 = *(const float4*)(pl + gh1 * Wd + c);
            if (ok2) a2 = *(const float4*)(pl + gh2 * Wd + c);
        }
    }
    {
        float* r1 = vsm + ty * VST + 2 + c;
        *(float2*)(r1)     = make_float2(thr(a1.x), thr(a1.y));
        *(float2*)(r1 + 2) = make_float2(thr(a1.z), thr(a1.w));
        if (has2) {
            float* r2 = vsm + k2 * VST + 2 + c;
            *(float2*)(r2)     = make_float2(thr(a2.x), thr(a2.y));
            *(float2*)(r2 + 2) = make_float2(thr(a2.z), thr(a2.w));
        }
    }

    // ring state
    float4 rp1  = make_float4(0.f, 0.f, 0.f, 0.f);   // m2d(p-1)
    float4 rp2  = rp1;                               // m2d(p-2)
    float4 cnd0 = rp1, cnd1 = rp1;                   // candidate ring (2 deep)

    float* outp = out + (size_t)d0 * (Hd * Wd) + (h0 + ty) * Wd + c;

    for (int p = 0; p < NP; ++p) {
        const int b = p & 1;
        float* vb = vsm + b * (LR * VST);
        float* wb = wsm + b * (LR * 512);

        __syncthreads();   // vsm[b] ready; wsm[b] free for rewrite

        // ---- prefetch plane p+1 into registers (hidden under compute) ----
        a1 = make_float4(0.f, 0.f, 0.f, 0.f); a2 = a1;
        {
            int dln = d0 - 1 + p;           // = d0-2 + (p+1)
            if (dln >= 0 && dln < Dd && (p + 1) < NP) {
                const float* pl = in + dln * (Hd * Wd);
                if (ok1) a1 = *(const float4*)(pl + gh1 * Wd + c);
                if (ok2) a2 = *(const float4*)(pl + gh2 * Wd + c);
            }
        }

        // ---- Phase B: W-max (window 5) for this thread's rows ----
        {
            const float* vr = vb + ty * VST + c;   // v cols c-2..c+5
            float4 u0 = *(const float4*)(vr);
            float4 u1 = *(const float4*)(vr + 4);
            float p01 = fmaxf(u0.x, u0.y), p12 = fmaxf(u0.y, u0.z);
            float p23 = fmaxf(u0.z, u0.w), p34 = fmaxf(u0.w, u1.x);
            float p45 = fmaxf(u1.x, u1.y), p56 = fmaxf(u1.y, u1.z);
            *(float4*)(wb + ty * 512 + c) = make_float4(
                fmaxf(fmaxf(p01, p23), u1.x),
                fmaxf(fmaxf(p12, p34), u1.y),
                fmaxf(fmaxf(p23, p45), u1.z),
                fmaxf(fmaxf(p34, p56), u1.w));
        }
        if (has2) {
            const float* vr = vb + k2 * VST + c;
            float4 u0 = *(const float4*)(vr);
            float4 u1 = *(const float4*)(vr + 4);
            float p01 = fmaxf(u0.x, u0.y), p12 = fmaxf(u0.y, u0.z);
            float p23 = fmaxf(u0.z, u0.w), p34 = fmaxf(u0.w, u1.x);
            float p45 = fmaxf(u1.x, u1.y), p56 = fmaxf(u1.y, u1.z);
            *(float4*)(wb + k2 * 512 + c) = make_float4(
                fmaxf(fmaxf(p01, p23), u1.x),
                fmaxf(fmaxf(p12, p34), u1.y),
                fmaxf(fmaxf(p23, p45), u1.z),
                fmaxf(fmaxf(p34, p56), u1.w));
        }
        // thresholded center for output row h0+ty (loaded row ty+2)
        float4 cen;
        {
            const float* cr = vb + (ty + 2) * VST + 2 + c;
            float2 cA = *(const float2*)(cr);
            float2 cB = *(const float2*)(cr + 2);
            cen = make_float4(cA.x, cA.y, cB.x, cB.y);
        }

        __syncthreads();   // wsm[b] ready; vsm[b] reads done

        // ---- Phase C: H-max (window 5) -> m2d; rings; emit ----
        const float* wr = wb + ty * 512 + c;
        float4 m = *(const float4*)(wr);
        m = fmax4(m, *(const float4*)(wr + 512));
        m = fmax4(m, *(const float4*)(wr + 1024));
        m = fmax4(m, *(const float4*)(wr + 1536));
        m = fmax4(m, *(const float4*)(wr + 2048));

        float4 s;
        s.x = (cen.x == m.x) ? cen.x : 0.f;
        s.y = (cen.y == m.y) ? cen.y : 0.f;
        s.z = (cen.z == m.z) ? cen.z : 0.f;
        s.w = (cen.w == m.w) ? cen.w : 0.f;

        float4 cn;
        cn.x = (s.x >= rp1.x && s.x >= rp2.x) ? s.x : 0.f;
        cn.y = (s.y >= rp1.y && s.y >= rp2.y) ? s.y : 0.f;
        cn.z = (s.z >= rp1.z && s.z >= rp2.z) ? s.z : 0.f;
        cn.w = (s.w >= rp1.w && s.w >= rp2.w) ? s.w : 0.f;

        if (p >= 4) {
            // cnd0 = cn(p-2); gates m2d(p-1)=rp1, m2d(p)=m
            float4 o;
            o.x = (cnd0.x >= rp1.x && cnd0.x >= m.x) ? cnd0.x : 0.f;
            o.y = (cnd0.y >= rp1.y && cnd0.y >= m.y) ? cnd0.y : 0.f;
            o.z = (cnd0.z >= rp1.z && cnd0.z >= m.z) ? cnd0.z : 0.f;
            o.w = (cnd0.w >= rp1.w && cnd0.w >= m.w) ? cnd0.w : 0.f;
            *(float4*)outp = o;
            outp += Hd * Wd;
        }

        cnd0 = cnd1; cnd1 = cn;
        rp2 = rp1;  rp1 = m;

        // ---- store prefetched plane into the other buffer ----
        {
            float* vn = vsm + (b ^ 1) * (LR * VST);
            float* r1 = vn + ty * VST + 2 + c;
            *(float2*)(r1)     = make_float2(thr(a1.x), thr(a1.y));
            *(float2*)(r1 + 2) = make_float2(thr(a1.z), thr(a1.w));
            if (has2) {
                float* r2 = vn + k2 * VST + 2 + c;
                *(float2*)(r2)     = make_float2(thr(a2.x), thr(a2.y));
                *(float2*)(r2 + 2) = make_float2(thr(a2.z), thr(a2.w));
            }
        }
    }
}

extern "C" void kernel_launch(void* const* d_in, const int* in_sizes, int n_in,
                              void* d_out, int out_size) {
    (void)in_sizes; (void)n_in; (void)out_size;
    const float* in = (const float*)d_in[0];
    float* out = (float*)d_out;

    const int smem_bytes = (2 * LR * VST + 2 * LR * 512) * (int)sizeof(float); // 99072
    cudaFuncSetAttribute(peak3d_kernel,
                         cudaFuncAttributeMaxDynamicSharedMemorySize, smem_bytes);

    dim3 block(128, 8);                 // 1024 threads
    dim3 grid(Hd / TH, Dd / DCH);       // 64 x 2 = 128 blocks (single wave)
    peak3d_kernel<<<grid, block, smem_bytes>>>(in, out);
}

// round 4
// speedup vs baseline: 2.0883x; 1.0903x over previous
#include <cuda_runtime.h>
#include <cuda_bf16.h>

// PostProcessor3D: threshold(0.9) -> 5x5x5 maxpool(stride1,pad2) -> strict peak mask.
// In: [64,512,512] f32.  Out: [64,512,512] f32.
//
// Block (128,8)=1024 threads covers full W=512 (float4/thread) x 8 H rows,
// marching 36 planes of a 32-deep D chunk. Grid 64x2 = 128 blocks (one wave).
//
// Separable order: H-max first (smem, 5 coalesced float4 LDS), then W-max in
// registers via warp shuffles (lane+-1); warp-edge columns via predicated
// float2 LDS on lanes 0/31 only. No second smem stage, ONE barrier per plane.
// -inf pad == 0 pad since thresholded values >= 0.
//
// D-dimension peak identity (2-deep candidate ring):
//   s(p)  = (cen(p)==m2d(p)) ? cen(p) : 0
//   cn(p) = (s >= m2d(p-1) && s >= m2d(p-2)) ? s : 0
//   out(q)= (cn(q) >= m2d(q+1) && cn(q) >= m2d(q+2)) ? cn(q) : 0, emitted p=q+2.

#define Wd 512
#define Hd 512
#define Dd 64
#define TH 8            // output rows per block
#define LR 12           // loaded rows (TH + 4)
#define DCH 32          // output planes per block
#define NP (DCH + 4)    // planes iterated
#define THRESH 0.9f

__device__ __forceinline__ float thr(float x) { return x > THRESH ? x : 0.f; }
__device__ __forceinline__ float4 thr4(float4 a) {
    return make_float4(thr(a.x), thr(a.y), thr(a.z), thr(a.w));
}
__device__ __forceinline__ float4 fmax4(float4 a, float4 b) {
    return make_float4(fmaxf(a.x, b.x), fmaxf(a.y, b.y),
                       fmaxf(a.z, b.z), fmaxf(a.w, b.w));
}

__global__ __launch_bounds__(1024, 1)
void peak3d_kernel(const float* __restrict__ in, float* __restrict__ out) {
    __shared__ float vsm[2][LR][512];      // thresholded planes, double-buffered

    const int tx   = threadIdx.x;          // 0..127
    const int ty   = threadIdx.y;          // 0..7
    const int lane = tx & 31;
    const int c    = tx << 2;              // column base (float4)
    const int h0   = blockIdx.x * TH;
    const int d0   = blockIdx.y * DCH;

    // warp-edge extension columns (hmax at c-2..c-1 for lane0, c+4..c+5 for lane31)
    const bool edgeL    = (lane == 0);
    const bool edgeR    = (lane == 31);
    const bool haveEdge = (edgeL && tx != 0) || (edgeR && tx != 127);
    const int  ec       = edgeL ? (c - 2) : (c + 4);

    const int  k2   = 8 + ty;
    const bool has2 = (ty < 4);
    const int  gh1  = h0 - 2 + ty;
    const int  gh2  = h0 - 2 + k2;
    const bool ok1  = ((unsigned)gh1 < (unsigned)Hd);
    const bool ok2  = has2 && (gh2 < Hd);

    // ---- prologue: fetch plane p=0 (dl = d0-2), store thresholded to buffer 0 ----
    float4 a1 = make_float4(0.f, 0.f, 0.f, 0.f), a2 = a1;
    {
        int dl = d0 - 2;
        if (dl >= 0) {
            const float* pl = in + dl * (Hd * Wd);
            if (ok1) a1 = *(const float4*)(pl + gh1 * Wd + c);
            if (ok2) a2 = *(const float4*)(pl + gh2 * Wd + c);
        }
    }
    *(float4*)(&vsm[0][ty][c]) = thr4(a1);
    if (has2) *(float4*)(&vsm[0][k2][c]) = thr4(a2);

    // ring state
    float4 rp1  = make_float4(0.f, 0.f, 0.f, 0.f);   // m2d(p-1)
    float4 rp2  = rp1;                               // m2d(p-2)
    float4 cnd0 = rp1, cnd1 = rp1;                   // cn ring (2 deep)

    float* outp = out + (size_t)d0 * (Hd * Wd) + (h0 + ty) * Wd + c;

    for (int p = 0; p < NP; ++p) {
        const int b = p & 1;
        const float* vb = &vsm[b][0][0];

        __syncthreads();   // vsm[b] stores done; prior reads of vsm[b^1] done

        // ---- prefetch plane p+1 into registers (hidden under compute) ----
        a1 = make_float4(0.f, 0.f, 0.f, 0.f); a2 = a1;
        {
            int dln = d0 - 1 + p;           // = d0-2 + (p+1)
            if (dln >= 0 && dln < Dd && (p + 1) < NP) {
                const float* pl = in + dln * (Hd * Wd);
                if (ok1) a1 = *(const float4*)(pl + gh1 * Wd + c);
                if (ok2) a2 = *(const float4*)(pl + gh2 * Wd + c);
            }
        }

        // ---- H-max (window 5) over loaded rows ty..ty+4 at cols c..c+3 ----
        const float* vr = vb + ty * 512 + c;
        float4 t0 = *(const float4*)(vr);
        float4 t1 = *(const float4*)(vr + 512);
        float4 t2 = *(const float4*)(vr + 1024);   // center row -> cen
        float4 t3 = *(const float4*)(vr + 1536);
        float4 t4 = *(const float4*)(vr + 2048);
        float4 cen = t2;
        float4 hm  = fmax4(fmax4(fmax4(t0, t1), fmax4(t2, t3)), t4);

        // edge lanes also compute H-max for the 2 extension columns
        float2 eh = make_float2(0.f, 0.f);
        if (haveEdge) {
            const float* ep = vb + ty * 512 + ec;
            float2 e0 = *(const float2*)(ep);
            float2 e1 = *(const float2*)(ep + 512);
            float2 e2 = *(const float2*)(ep + 1024);
            float2 e3 = *(const float2*)(ep + 1536);
            float2 e4 = *(const float2*)(ep + 2048);
            eh.x = fmaxf(fmaxf(fmaxf(e0.x, e1.x), fmaxf(e2.x, e3.x)), e4.x);
            eh.y = fmaxf(fmaxf(fmaxf(e0.y, e1.y), fmaxf(e2.y, e3.y)), e4.y);
        }

        // ---- W-max (window 5) in registers via shuffles ----
        float l2 = __shfl_up_sync(0xffffffffu, hm.z, 1);
        float l1 = __shfl_up_sync(0xffffffffu, hm.w, 1);
        float r4 = __shfl_down_sync(0xffffffffu, hm.x, 1);
        float r5 = __shfl_down_sync(0xffffffffu, hm.y, 1);
        if (edgeL) { l2 = eh.x; l1 = eh.y; }   // eh==0 at global W edge
        if (edgeR) { r4 = eh.x; r5 = eh.y; }

        float m01 = fmaxf(hm.x, hm.y);
        float m12 = fmaxf(hm.y, hm.z);
        float m23 = fmaxf(hm.z, hm.w);
        float4 m;  // m2d(p) for cols c..c+3
        m.x = fmaxf(fmaxf(l2, l1), fmaxf(m01, hm.z));
        m.y = fmaxf(l1, fmaxf(m01, m23));
        m.z = fmaxf(fmaxf(m01, m23), r4);
        m.w = fmaxf(fmaxf(m12, hm.w), fmaxf(r4, r5));

        // ---- D rings + emit ----
        float4 s;
        s.x = (cen.x == m.x) ? cen.x : 0.f;
        s.y = (cen.y == m.y) ? cen.y : 0.f;
        s.z = (cen.z == m.z) ? cen.z : 0.f;
        s.w = (cen.w == m.w) ? cen.w : 0.f;

        float4 cn;
        cn.x = (s.x >= rp1.x && s.x >= rp2.x) ? s.x : 0.f;
        cn.y = (s.y >= rp1.y && s.y >= rp2.y) ? s.y : 0.f;
        cn.z = (s.z >= rp1.z && s.z >= rp2.z) ? s.z : 0.f;
        cn.w = (s.w >= rp1.w && s.w >= rp2.w) ? s.w : 0.f;

        if (p >= 4) {
            // cnd0 = cn(p-2); gates m2d(p-1)=rp1, m2d(p)=m
            float4 o;
            o.x = (cnd0.x >= rp1.x && cnd0.x >= m.x) ? cnd0.x : 0.f;
            o.y = (cnd0.y >= rp1.y && cnd0.y >= m.y) ? cnd0.y : 0.f;
            o.z = (cnd0.z >= rp1.z && cnd0.z >= m.z) ? cnd0.z : 0.f;
            o.w = (cnd0.w >= rp1.w && cnd0.w >= m.w) ? cnd0.w : 0.f;
            *(float4*)outp = o;
            outp += Hd * Wd;
        }

        cnd0 = cnd1; cnd1 = cn;
        rp2  = rp1;  rp1  = m;

        // ---- store prefetched plane (thresholded) into the other buffer ----
        *(float4*)(&vsm[b ^ 1][ty][c]) = thr4(a1);
        if (has2) *(float4*)(&vsm[b ^ 1][k2][c]) = thr4(a2);
    }
}

extern "C" void kernel_launch(void* const* d_in, const int* in_sizes, int n_in,
                              void* d_out, int out_size) {
    (void)in_sizes; (void)n_in; (void)out_size;
    const float* in = (const float*)d_in[0];
    float* out = (float*)d_out;

    dim3 block(128, 8);                 // 1024 threads
    dim3 grid(Hd / TH, Dd / DCH);       // 64 x 2 = 128 blocks (single wave)
    peak3d_kernel<<<grid, block>>>(in, out);
}